// round 13
// baseline (speedup 1.0000x reference)
#include <cuda_runtime.h>
#include <cstdint>

#define SEQ 4096
#define DIN 1024
#define NH 8
#define DH 64          // hidden per head
#define DV 128         // NUM_OUT per head
#define DKQ 512        // NH*DH
#define DVA 1024       // NH*DV

// ---------------- scratch (static device allocations are allowed) ----------
static __device__ float g_K[SEQ * DKQ];            // scaled keys-projection (attention "Q")
static __device__ float g_Q[SEQ * DKQ];            // queries-projection (attention "K")
static __device__ float g_V[SEQ * DVA];
static __device__ float g_Oh[NH][SEQ * DV];        // per-head attention outputs

// ---------------- helpers ---------------------------------------------------
__device__ __forceinline__ uint32_t f2tf(float x) {
    uint32_t r;
    asm("cvt.rna.tf32.f32 %0, %1;" : "=r"(r) : "f"(x));
    return r;
}
__device__ __forceinline__ uint32_t fu(float x) { return __float_as_uint(x); }

__device__ __forceinline__ void mma8(float c[4], const uint32_t a[4], const uint32_t b[2]) {
    asm volatile(
        "mma.sync.aligned.m16n8k8.row.col.f32.tf32.tf32.f32 "
        "{%0,%1,%2,%3}, {%4,%5,%6,%7}, {%8,%9}, {%0,%1,%2,%3};\n"
        : "+f"(c[0]), "+f"(c[1]), "+f"(c[2]), "+f"(c[3])
        : "r"(a[0]), "r"(a[1]), "r"(a[2]), "r"(a[3]), "r"(b[0]), "r"(b[1]));
}

// ===========================================================================
// Kernel 1: fused projections  Y = x @ W^T + b  (times scale for K)
//   block tile 128x64, K-tile 32, 256 threads (8 warps, 4x2), tf32 MMA
//   grid.y: 0..7 -> Wk tiles, 8..15 -> Wq tiles, 16..31 -> Wv tiles
// ===========================================================================
#define PBM 128
#define PBN 64
#define PBK 32
#define PLDA 36
#define PNKT (DIN / PBK)   // 32

__global__ void __launch_bounds__(256) proj_kernel(
    const float* __restrict__ x,
    const float* __restrict__ Wk, const float* __restrict__ bk,
    const float* __restrict__ Wq, const float* __restrict__ bq,
    const float* __restrict__ Wv, const float* __restrict__ bv)
{
    __shared__ __align__(16) float As[PBM * PLDA];
    __shared__ __align__(16) float Bs[PBN * PLDA];

    int nt = blockIdx.y;
    const float* W;
    const float* bias;
    float* Y;
    int ncols;
    float scale;
    if (nt < 8)       { W = Wk; bias = bk; Y = g_K; ncols = DKQ; scale = 0.125f; }
    else if (nt < 16) { W = Wq; bias = bq; Y = g_Q; ncols = DKQ; scale = 1.0f; nt -= 8; }
    else              { W = Wv; bias = bv; Y = g_V; ncols = DVA; scale = 1.0f; nt -= 16; }
    const int n0 = nt * PBN;
    const int m0 = blockIdx.x * PBM;

    const int tid = threadIdx.x, lane = tid & 31, warp = tid >> 5;
    const int g = lane >> 2, t = lane & 3;
    const int wm = warp & 3, wn = warp >> 2;   // warp tile: rows wm*32, cols wn*32

    const int lr  = tid >> 3;   // loader row 0..31
    const int lc4 = tid & 7;    // loader float4 col 0..7

    const float* xp = x + (size_t)(m0 + lr) * DIN + lc4 * 4;
    const float* wp = W + (size_t)(n0 + lr) * DIN + lc4 * 4;

    float4 xa[4];
    float4 wa[2];
    float acc[2][4][4];
#pragma unroll
    for (int i = 0; i < 2; i++)
#pragma unroll
        for (int j = 0; j < 4; j++)
#pragma unroll
            for (int k = 0; k < 4; k++) acc[i][j][k] = 0.f;

    // prologue load + store
#pragma unroll
    for (int r = 0; r < 4; r++) xa[r] = *(const float4*)(xp + (size_t)r * 32 * DIN);
#pragma unroll
    for (int r = 0; r < 2; r++) wa[r] = *(const float4*)(wp + (size_t)r * 32 * DIN);
#pragma unroll
    for (int r = 0; r < 4; r++) {
        uint4 u4;
        u4.x = f2tf(xa[r].x); u4.y = f2tf(xa[r].y); u4.z = f2tf(xa[r].z); u4.w = f2tf(xa[r].w);
        *reinterpret_cast<uint4*>(&As[(lr + r * 32) * PLDA + lc4 * 4]) = u4;
    }
#pragma unroll
    for (int r = 0; r < 2; r++) {
        uint4 u4;
        u4.x = f2tf(wa[r].x); u4.y = f2tf(wa[r].y); u4.z = f2tf(wa[r].z); u4.w = f2tf(wa[r].w);
        *reinterpret_cast<uint4*>(&Bs[(lr + r * 32) * PLDA + lc4 * 4]) = u4;
    }
    __syncthreads();

    for (int kt = 0; kt < PNKT; kt++) {
        const int knext = (kt + 1) * PBK;
        if (kt + 1 < PNKT) {
#pragma unroll
            for (int r = 0; r < 4; r++) xa[r] = *(const float4*)(xp + (size_t)r * 32 * DIN + knext);
#pragma unroll
            for (int r = 0; r < 2; r++) wa[r] = *(const float4*)(wp + (size_t)r * 32 * DIN + knext);
        }
        // compute from smem
#pragma unroll
        for (int ks = 0; ks < 4; ks++) {
            const int k0 = ks * 8;
            uint32_t afr[2][4];
#pragma unroll
            for (int ms = 0; ms < 2; ms++) {
                const float* Ab = &As[(wm * 32 + ms * 16) * PLDA + k0];
                afr[ms][0] = fu(Ab[g * PLDA + t]);
                afr[ms][1] = fu(Ab[(g + 8) * PLDA + t]);
                afr[ms][2] = fu(Ab[g * PLDA + t + 4]);
                afr[ms][3] = fu(Ab[(g + 8) * PLDA + t + 4]);
            }
#pragma unroll
            for (int ns = 0; ns < 4; ns++) {
                const float* Bb = &Bs[(wn * 32 + ns * 8 + g) * PLDA + k0];
                uint32_t bfr[2];
                bfr[0] = fu(Bb[t]);
                bfr[1] = fu(Bb[t + 4]);
#pragma unroll
                for (int ms = 0; ms < 2; ms++) mma8(acc[ms][ns], afr[ms], bfr);
            }
        }
        __syncthreads();
        if (kt + 1 < PNKT) {
#pragma unroll
            for (int r = 0; r < 4; r++) {
                uint4 u4;
                u4.x = f2tf(xa[r].x); u4.y = f2tf(xa[r].y); u4.z = f2tf(xa[r].z); u4.w = f2tf(xa[r].w);
                *reinterpret_cast<uint4*>(&As[(lr + r * 32) * PLDA + lc4 * 4]) = u4;
            }
#pragma unroll
            for (int r = 0; r < 2; r++) {
                uint4 u4;
                u4.x = f2tf(wa[r].x); u4.y = f2tf(wa[r].y); u4.z = f2tf(wa[r].z); u4.w = f2tf(wa[r].w);
                *reinterpret_cast<uint4*>(&Bs[(lr + r * 32) * PLDA + lc4 * 4]) = u4;
            }
            __syncthreads();
        }
    }

    // epilogue: bias + scale
#pragma unroll
    for (int ms = 0; ms < 2; ms++) {
        const int row = m0 + wm * 32 + ms * 16;
#pragma unroll
        for (int ns = 0; ns < 4; ns++) {
            const int col = n0 + wn * 32 + ns * 8 + 2 * t;
            const float b0 = __ldg(&bias[col]);
            const float b1 = __ldg(&bias[col + 1]);
            float2 v0 = make_float2((acc[ms][ns][0] + b0) * scale, (acc[ms][ns][1] + b1) * scale);
            float2 v1 = make_float2((acc[ms][ns][2] + b0) * scale, (acc[ms][ns][3] + b1) * scale);
            *reinterpret_cast<float2*>(&Y[(size_t)(row + g) * ncols + col]) = v0;
            *reinterpret_cast<float2*>(&Y[(size_t)(row + g + 8) * ncols + col]) = v1;
        }
    }
}

// ===========================================================================
// Kernel 2: flash attention per (i-tile of 64, head)
//   attention Q := g_K rows (already scaled), K := g_Q rows, V := g_V
//   8 warps in 4(M) x 2(N); online softmax over j; tf32 MMAs, fp32 stats
// ===========================================================================
#define TI 64
#define TJ 64
#define SQL 68   // smem row stride for Qs/Ks/Ss
#define SVL 68   // smem row stride for Vs (transposed [e][j])

static constexpr int ATTN_SMEM_FLOATS = 64 * SQL * 3 + 128 * SVL + 192;
static constexpr int ATTN_SMEM_BYTES  = ATTN_SMEM_FLOATS * 4;   // 87808 B

__global__ void __launch_bounds__(256, 2) attn_kernel() {
    extern __shared__ __align__(16) float sm[];
    float* Qs   = sm;                    // [64][SQL] tf32
    float* Ks   = Qs + 64 * SQL;         // [64][SQL] tf32
    float* Ss   = Ks + 64 * SQL;         // [64][SQL] fp32 scores -> tf32 P
    float* Vs   = Ss + 64 * SQL;         // [128][SVL] tf32, transposed (e, j)
    float* mrow = Vs + 128 * SVL;        // [64]
    float* lrow = mrow + 64;             // [64]
    float* arow = lrow + 64;             // [64]

    const int h  = blockIdx.y;
    const int i0 = blockIdx.x * TI;
    const int tid = threadIdx.x, lane = tid & 31, warp = tid >> 5;
    const int g = lane >> 2, t = lane & 3;
    const int wm = warp & 3, wn = warp >> 2;

    // load Q' tile once (rows i0.., head h), convert to tf32
    {
        const float* src = g_K + (size_t)i0 * DKQ + h * DH;
        for (int idx = tid; idx < 64 * 16; idx += 256) {
            const int r = idx >> 4, c4 = idx & 15;
            float4 v = *(const float4*)(src + (size_t)r * DKQ + c4 * 4);
            uint4 u4;
            u4.x = f2tf(v.x); u4.y = f2tf(v.y); u4.z = f2tf(v.z); u4.w = f2tf(v.w);
            *reinterpret_cast<uint4*>(&Qs[r * SQL + c4 * 4]) = u4;
        }
    }
    if (tid < 64) { mrow[tid] = -3.0e38f; lrow[tid] = 0.f; }

    float Oacc[8][4];
#pragma unroll
    for (int i = 0; i < 8; i++)
#pragma unroll
        for (int j = 0; j < 4; j++) Oacc[i][j] = 0.f;

    for (int jt = 0; jt < SEQ / TJ; ++jt) {
        __syncthreads();   // previous iteration fully done with Ks/Vs/Ss
        // load K' tile (g_Q) -> Ks, tf32
        {
            const float* src = g_Q + (size_t)(jt * TJ) * DKQ + h * DH;
            for (int idx = tid; idx < 64 * 16; idx += 256) {
                const int r = idx >> 4, c4 = idx & 15;
                float4 v = *(const float4*)(src + (size_t)r * DKQ + c4 * 4);
                uint4 u4;
                u4.x = f2tf(v.x); u4.y = f2tf(v.y); u4.z = f2tf(v.z); u4.w = f2tf(v.w);
                *reinterpret_cast<uint4*>(&Ks[r * SQL + c4 * 4]) = u4;
            }
        }
        // load V tile transposed -> Vs[e][j], tf32
        {
            const float* src = g_V + (size_t)(jt * TJ) * DVA + h * DV;
            for (int idx = tid; idx < 64 * 128; idx += 256) {
                const int j = idx >> 7, e = idx & 127;
                Vs[e * SVL + j] = __uint_as_float(f2tf(src[(size_t)j * DVA + e]));
            }
        }
        __syncthreads();

        // --- S = Q' K'^T  (warp tile 16 x 32) ---
        float Sacc[4][4];
#pragma unroll
        for (int i = 0; i < 4; i++)
#pragma unroll
            for (int j = 0; j < 4; j++) Sacc[i][j] = 0.f;
#pragma unroll
        for (int ks = 0; ks < 8; ks++) {
            const int k0 = ks * 8;
            uint32_t a[4];
            const float* Ab = &Qs[(wm * 16) * SQL + k0];
            a[0] = fu(Ab[g * SQL + t]);
            a[1] = fu(Ab[(g + 8) * SQL + t]);
            a[2] = fu(Ab[g * SQL + t + 4]);
            a[3] = fu(Ab[(g + 8) * SQL + t + 4]);
#pragma unroll
            for (int ns = 0; ns < 4; ns++) {
                const float* Bb = &Ks[(wn * 32 + ns * 8 + g) * SQL + k0];
                uint32_t b[2] = { fu(Bb[t]), fu(Bb[t + 4]) };
                mma8(Sacc[ns], a, b);
            }
        }
        // write scores to smem
#pragma unroll
        for (int ns = 0; ns < 4; ns++) {
            const int col = wn * 32 + ns * 8 + 2 * t;
            *reinterpret_cast<float2*>(&Ss[(wm * 16 + g) * SQL + col]) =
                make_float2(Sacc[ns][0], Sacc[ns][1]);
            *reinterpret_cast<float2*>(&Ss[(wm * 16 + g + 8) * SQL + col]) =
                make_float2(Sacc[ns][2], Sacc[ns][3]);
        }
        __syncthreads();

        // --- online softmax (4 threads per row, 16 cols each) ---
        {
            const int row = tid >> 2, q = tid & 3;
            float* Sr = &Ss[row * SQL + q * 16];
            float tmax = -3.0e38f;
#pragma unroll
            for (int c = 0; c < 16; c++) tmax = fmaxf(tmax, Sr[c]);
            tmax = fmaxf(tmax, __shfl_xor_sync(0xffffffffu, tmax, 1));
            tmax = fmaxf(tmax, __shfl_xor_sync(0xffffffffu, tmax, 2));
            const float mold = mrow[row];
            const float mnew = fmaxf(mold, tmax);
            float s = 0.f;
#pragma unroll
            for (int c = 0; c < 16; c++) {
                const float p = __expf(Sr[c] - mnew);
                s += p;
                Sr[c] = __uint_as_float(f2tf(p));   // P in tf32 for second MMA
            }
            s += __shfl_xor_sync(0xffffffffu, s, 1);
            s += __shfl_xor_sync(0xffffffffu, s, 2);
            if (q == 0) {
                const float al = __expf(mold - mnew);
                arow[row] = al;
                mrow[row] = mnew;
                lrow[row] = lrow[row] * al + s;
            }
        }
        __syncthreads();

        // --- rescale O and accumulate O += P @ V (warp tile 16 x 64) ---
        {
            const float a0 = arow[wm * 16 + g];
            const float a1 = arow[wm * 16 + g + 8];
#pragma unroll
            for (int ns = 0; ns < 8; ns++) {
                Oacc[ns][0] *= a0; Oacc[ns][1] *= a0;
                Oacc[ns][2] *= a1; Oacc[ns][3] *= a1;
            }
#pragma unroll
            for (int ks = 0; ks < 8; ks++) {
                const int k0 = ks * 8;
                uint32_t a[4];
                const float* Ab = &Ss[(wm * 16) * SQL + k0];
                a[0] = fu(Ab[g * SQL + t]);
                a[1] = fu(Ab[(g + 8) * SQL + t]);
                a[2] = fu(Ab[g * SQL + t + 4]);
                a[3] = fu(Ab[(g + 8) * SQL + t + 4]);
#pragma unroll
                for (int ns = 0; ns < 8; ns++) {
                    const float* Bb = &Vs[(wn * 64 + ns * 8 + g) * SVL + k0];
                    uint32_t b[2] = { fu(Bb[t]), fu(Bb[t + 4]) };
                    mma8(Oacc[ns], a, b);
                }
            }
        }
    }

    __syncthreads();
    // epilogue: divide by softmax denominator, store per-head output
    {
        const float r0 = 1.f / lrow[wm * 16 + g];
        const float r1 = 1.f / lrow[wm * 16 + g + 8];
        float* dst = g_Oh[h] + (size_t)(i0 + wm * 16) * DV + wn * 64;
#pragma unroll
        for (int ns = 0; ns < 8; ns++) {
            const int col = ns * 8 + 2 * t;
            *reinterpret_cast<float2*>(&dst[(size_t)g * DV + col]) =
                make_float2(Oacc[ns][0] * r0, Oacc[ns][1] * r0);
            *reinterpret_cast<float2*>(&dst[(size_t)(g + 8) * DV + col]) =
                make_float2(Oacc[ns][2] * r1, Oacc[ns][3] * r1);
        }
    }
}

// ===========================================================================
// Kernel 3: sum heads + LayerNorm over last dim (128)
// ===========================================================================
__global__ void __launch_bounds__(128) ln_kernel(
    const float* __restrict__ ln_w, const float* __restrict__ ln_b,
    float* __restrict__ out)
{
    const int i = blockIdx.x;
    const int e = threadIdx.x;     // 0..127
    const int lane = e & 31, w = e >> 5;

    float s = 0.f;
#pragma unroll
    for (int h = 0; h < NH; h++) s += g_Oh[h][(size_t)i * DV + e];

    __shared__ float red[4];
    float v = s;
#pragma unroll
    for (int o = 16; o > 0; o >>= 1) v += __shfl_xor_sync(0xffffffffu, v, o);
    if (lane == 0) red[w] = v;
    __syncthreads();
    const float mean = (red[0] + red[1] + red[2] + red[3]) * (1.f / 128.f);
    const float d = s - mean;

    float vv = d * d;
#pragma unroll
    for (int o = 16; o > 0; o >>= 1) vv += __shfl_xor_sync(0xffffffffu, vv, o);
    __syncthreads();
    if (lane == 0) red[w] = vv;
    __syncthreads();
    const float var = (red[0] + red[1] + red[2] + red[3]) * (1.f / 128.f);

    out[(size_t)i * DV + e] = d * rsqrtf(var + 1e-5f) * __ldg(&ln_w[e]) + __ldg(&ln_b[e]);
}

// ===========================================================================
extern "C" void kernel_launch(void* const* d_in, const int* in_sizes, int n_in,
                              void* d_out, int out_size) {
    (void)in_sizes; (void)n_in; (void)out_size;
    const float* x  = (const float*)d_in[0];
    const float* Wk = (const float*)d_in[1];
    const float* bk = (const float*)d_in[2];
    const float* Wq = (const float*)d_in[3];
    const float* bq = (const float*)d_in[4];
    const float* Wv = (const float*)d_in[5];
    const float* bv = (const float*)d_in[6];
    const float* lw = (const float*)d_in[7];
    const float* lb = (const float*)d_in[8];
    float* out = (float*)d_out;

    // projections: grid.y = 8 (Wk) + 8 (Wq) + 16 (Wv) tiles of 64 cols
    proj_kernel<<<dim3(SEQ / PBM, 32), 256>>>(x, Wk, bk, Wq, bq, Wv, bv);

    cudaFuncSetAttribute(attn_kernel, cudaFuncAttributeMaxDynamicSharedMemorySize,
                         ATTN_SMEM_BYTES);
    attn_kernel<<<dim3(SEQ / TI, NH), 256, ATTN_SMEM_BYTES>>>();

    ln_kernel<<<SEQ, 128>>>(lw, lb, out);
}

// round 14
// speedup vs baseline: 1.0154x; 1.0154x over previous
#include <cuda_runtime.h>
#include <cstdint>

#define SEQ 4096
#define DIN 1024
#define NH 8
#define DH 64          // hidden per head
#define DV 128         // NUM_OUT per head
#define DKQ 512        // NH*DH
#define DVA 1024       // NH*DV

// ---------------- scratch (static device allocations are allowed) ----------
static __device__ float g_K[SEQ * DKQ];            // scaled keys-projection (attention "Q")
static __device__ float g_Q[SEQ * DKQ];            // queries-projection (attention "K")
static __device__ float g_V[SEQ * DVA];
static __device__ float g_Oh[NH][SEQ * DV];        // per-head attention outputs

// ---------------- helpers ---------------------------------------------------
__device__ __forceinline__ uint32_t f2tf(float x) {
    uint32_t r;
    asm("cvt.rna.tf32.f32 %0, %1;" : "=r"(r) : "f"(x));
    return r;
}
__device__ __forceinline__ uint32_t fu(float x) { return __float_as_uint(x); }

__device__ __forceinline__ void mma8(float c[4], const uint32_t a[4], const uint32_t b[2]) {
    asm volatile(
        "mma.sync.aligned.m16n8k8.row.col.f32.tf32.tf32.f32 "
        "{%0,%1,%2,%3}, {%4,%5,%6,%7}, {%8,%9}, {%0,%1,%2,%3};\n"
        : "+f"(c[0]), "+f"(c[1]), "+f"(c[2]), "+f"(c[3])
        : "r"(a[0]), "r"(a[1]), "r"(a[2]), "r"(a[3]), "r"(b[0]), "r"(b[1]));
}

// ===========================================================================
// Kernel 1: fused projections  Y = x @ W^T + b  (times scale for K)
//   block tile 128x64, K-tile 32, 256 threads (8 warps, 4x2), tf32 MMA
//   grid.y: 0..7 -> Wk tiles, 8..15 -> Wq tiles, 16..31 -> Wv tiles
// ===========================================================================
#define PBM 128
#define PBN 64
#define PBK 32
#define PLDA 36
#define PNKT (DIN / PBK)   // 32

__global__ void __launch_bounds__(256) proj_kernel(
    const float* __restrict__ x,
    const float* __restrict__ Wk, const float* __restrict__ bk,
    const float* __restrict__ Wq, const float* __restrict__ bq,
    const float* __restrict__ Wv, const float* __restrict__ bv)
{
    __shared__ __align__(16) float As[PBM * PLDA];
    __shared__ __align__(16) float Bs[PBN * PLDA];

    int nt = blockIdx.y;
    const float* W;
    const float* bias;
    float* Y;
    int ncols;
    float scale;
    if (nt < 8)       { W = Wk; bias = bk; Y = g_K; ncols = DKQ; scale = 0.125f; }
    else if (nt < 16) { W = Wq; bias = bq; Y = g_Q; ncols = DKQ; scale = 1.0f; nt -= 8; }
    else              { W = Wv; bias = bv; Y = g_V; ncols = DVA; scale = 1.0f; nt -= 16; }
    const int n0 = nt * PBN;
    const int m0 = blockIdx.x * PBM;

    const int tid = threadIdx.x, lane = tid & 31, warp = tid >> 5;
    const int g = lane >> 2, t = lane & 3;
    const int wm = warp & 3, wn = warp >> 2;   // warp tile: rows wm*32, cols wn*32

    const int lr  = tid >> 3;   // loader row 0..31
    const int lc4 = tid & 7;    // loader float4 col 0..7

    const float* xp = x + (size_t)(m0 + lr) * DIN + lc4 * 4;
    const float* wp = W + (size_t)(n0 + lr) * DIN + lc4 * 4;

    float4 xa[4];
    float4 wa[2];
    float acc[2][4][4];
#pragma unroll
    for (int i = 0; i < 2; i++)
#pragma unroll
        for (int j = 0; j < 4; j++)
#pragma unroll
            for (int k = 0; k < 4; k++) acc[i][j][k] = 0.f;

    // prologue load + store
#pragma unroll
    for (int r = 0; r < 4; r++) xa[r] = *(const float4*)(xp + (size_t)r * 32 * DIN);
#pragma unroll
    for (int r = 0; r < 2; r++) wa[r] = *(const float4*)(wp + (size_t)r * 32 * DIN);
#pragma unroll
    for (int r = 0; r < 4; r++) {
        uint4 u4;
        u4.x = f2tf(xa[r].x); u4.y = f2tf(xa[r].y); u4.z = f2tf(xa[r].z); u4.w = f2tf(xa[r].w);
        *reinterpret_cast<uint4*>(&As[(lr + r * 32) * PLDA + lc4 * 4]) = u4;
    }
#pragma unroll
    for (int r = 0; r < 2; r++) {
        uint4 u4;
        u4.x = f2tf(wa[r].x); u4.y = f2tf(wa[r].y); u4.z = f2tf(wa[r].z); u4.w = f2tf(wa[r].w);
        *reinterpret_cast<uint4*>(&Bs[(lr + r * 32) * PLDA + lc4 * 4]) = u4;
    }
    __syncthreads();

    for (int kt = 0; kt < PNKT; kt++) {
        const int knext = (kt + 1) * PBK;
        if (kt + 1 < PNKT) {
#pragma unroll
            for (int r = 0; r < 4; r++) xa[r] = *(const float4*)(xp + (size_t)r * 32 * DIN + knext);
#pragma unroll
            for (int r = 0; r < 2; r++) wa[r] = *(const float4*)(wp + (size_t)r * 32 * DIN + knext);
        }
        // compute from smem
#pragma unroll
        for (int ks = 0; ks < 4; ks++) {
            const int k0 = ks * 8;
            uint32_t afr[2][4];
#pragma unroll
            for (int ms = 0; ms < 2; ms++) {
                const float* Ab = &As[(wm * 32 + ms * 16) * PLDA + k0];
                afr[ms][0] = fu(Ab[g * PLDA + t]);
                afr[ms][1] = fu(Ab[(g + 8) * PLDA + t]);
                afr[ms][2] = fu(Ab[g * PLDA + t + 4]);
                afr[ms][3] = fu(Ab[(g + 8) * PLDA + t + 4]);
            }
#pragma unroll
            for (int ns = 0; ns < 4; ns++) {
                const float* Bb = &Bs[(wn * 32 + ns * 8 + g) * PLDA + k0];
                uint32_t bfr[2];
                bfr[0] = fu(Bb[t]);
                bfr[1] = fu(Bb[t + 4]);
#pragma unroll
                for (int ms = 0; ms < 2; ms++) mma8(acc[ms][ns], afr[ms], bfr);
            }
        }
        __syncthreads();
        if (kt + 1 < PNKT) {
#pragma unroll
            for (int r = 0; r < 4; r++) {
                uint4 u4;
                u4.x = f2tf(xa[r].x); u4.y = f2tf(xa[r].y); u4.z = f2tf(xa[r].z); u4.w = f2tf(xa[r].w);
                *reinterpret_cast<uint4*>(&As[(lr + r * 32) * PLDA + lc4 * 4]) = u4;
            }
#pragma unroll
            for (int r = 0; r < 2; r++) {
                uint4 u4;
                u4.x = f2tf(wa[r].x); u4.y = f2tf(wa[r].y); u4.z = f2tf(wa[r].z); u4.w = f2tf(wa[r].w);
                *reinterpret_cast<uint4*>(&Bs[(lr + r * 32) * PLDA + lc4 * 4]) = u4;
            }
            __syncthreads();
        }
    }

    // epilogue: bias + scale
#pragma unroll
    for (int ms = 0; ms < 2; ms++) {
        const int row = m0 + wm * 32 + ms * 16;
#pragma unroll
        for (int ns = 0; ns < 4; ns++) {
            const int col = n0 + wn * 32 + ns * 8 + 2 * t;
            const float b0 = __ldg(&bias[col]);
            const float b1 = __ldg(&bias[col + 1]);
            float2 v0 = make_float2((acc[ms][ns][0] + b0) * scale, (acc[ms][ns][1] + b1) * scale);
            float2 v1 = make_float2((acc[ms][ns][2] + b0) * scale, (acc[ms][ns][3] + b1) * scale);
            *reinterpret_cast<float2*>(&Y[(size_t)(row + g) * ncols + col]) = v0;
            *reinterpret_cast<float2*>(&Y[(size_t)(row + g + 8) * ncols + col]) = v1;
        }
    }
}

// ===========================================================================
// Kernel 2: flash attention per (i-tile of 64, head)
//   attention Q := g_K rows (already scaled), K := g_Q rows, V := g_V
//   8 warps in 4(M) x 2(N); online softmax over j; tf32 MMAs, fp32 stats
// ===========================================================================
#define TI 64
#define TJ 64
#define SQL 68   // smem row stride for Qs/Ks/Ss
#define SVL 68   // smem row stride for Vs (transposed [e][j])

static constexpr int ATTN_SMEM_FLOATS = 64 * SQL * 3 + 128 * SVL + 192;
static constexpr int ATTN_SMEM_BYTES  = ATTN_SMEM_FLOATS * 4;   // 87808 B

__global__ void __launch_bounds__(256, 2) attn_kernel() {
    extern __shared__ __align__(16) float sm[];
    float* Qs   = sm;                    // [64][SQL] tf32
    float* Ks   = Qs + 64 * SQL;         // [64][SQL] tf32
    float* Ss   = Ks + 64 * SQL;         // [64][SQL] fp32 scores -> tf32 P
    float* Vs   = Ss + 64 * SQL;         // [128][SVL] tf32, transposed (e, j)
    float* mrow = Vs + 128 * SVL;        // [64]
    float* lrow = mrow + 64;             // [64]
    float* arow = lrow + 64;             // [64]

    const int h  = blockIdx.y;
    const int i0 = blockIdx.x * TI;
    const int tid = threadIdx.x, lane = tid & 31, warp = tid >> 5;
    const int g = lane >> 2, t = lane & 3;
    const int wm = warp & 3, wn = warp >> 2;

    // load Q' tile once (rows i0.., head h), convert to tf32
    {
        const float* src = g_K + (size_t)i0 * DKQ + h * DH;
        for (int idx = tid; idx < 64 * 16; idx += 256) {
            const int r = idx >> 4, c4 = idx & 15;
            float4 v = *(const float4*)(src + (size_t)r * DKQ + c4 * 4);
            uint4 u4;
            u4.x = f2tf(v.x); u4.y = f2tf(v.y); u4.z = f2tf(v.z); u4.w = f2tf(v.w);
            *reinterpret_cast<uint4*>(&Qs[r * SQL + c4 * 4]) = u4;
        }
    }
    if (tid < 64) { mrow[tid] = -3.0e38f; lrow[tid] = 0.f; }

    float Oacc[8][4];
#pragma unroll
    for (int i = 0; i < 8; i++)
#pragma unroll
        for (int j = 0; j < 4; j++) Oacc[i][j] = 0.f;

    for (int jt = 0; jt < SEQ / TJ; ++jt) {
        __syncthreads();   // previous iteration fully done with Ks/Vs/Ss
        // load K' tile (g_Q) -> Ks, tf32
        {
            const float* src = g_Q + (size_t)(jt * TJ) * DKQ + h * DH;
            for (int idx = tid; idx < 64 * 16; idx += 256) {
                const int r = idx >> 4, c4 = idx & 15;
                float4 v = *(const float4*)(src + (size_t)r * DKQ + c4 * 4);
                uint4 u4;
                u4.x = f2tf(v.x); u4.y = f2tf(v.y); u4.z = f2tf(v.z); u4.w = f2tf(v.w);
                *reinterpret_cast<uint4*>(&Ks[r * SQL + c4 * 4]) = u4;
            }
        }
        // load V tile transposed -> Vs[e][j], tf32
        {
            const float* src = g_V + (size_t)(jt * TJ) * DVA + h * DV;
            for (int idx = tid; idx < 64 * 128; idx += 256) {
                const int j = idx >> 7, e = idx & 127;
                Vs[e * SVL + j] = __uint_as_float(f2tf(src[(size_t)j * DVA + e]));
            }
        }
        __syncthreads();

        // --- S = Q' K'^T  (warp tile 16 x 32) ---
        float Sacc[4][4];
#pragma unroll
        for (int i = 0; i < 4; i++)
#pragma unroll
            for (int j = 0; j < 4; j++) Sacc[i][j] = 0.f;
#pragma unroll
        for (int ks = 0; ks < 8; ks++) {
            const int k0 = ks * 8;
            uint32_t a[4];
            const float* Ab = &Qs[(wm * 16) * SQL + k0];
            a[0] = fu(Ab[g * SQL + t]);
            a[1] = fu(Ab[(g + 8) * SQL + t]);
            a[2] = fu(Ab[g * SQL + t + 4]);
            a[3] = fu(Ab[(g + 8) * SQL + t + 4]);
#pragma unroll
            for (int ns = 0; ns < 4; ns++) {
                const float* Bb = &Ks[(wn * 32 + ns * 8 + g) * SQL + k0];
                uint32_t b[2] = { fu(Bb[t]), fu(Bb[t + 4]) };
                mma8(Sacc[ns], a, b);
            }
        }
        // write scores to smem
#pragma unroll
        for (int ns = 0; ns < 4; ns++) {
            const int col = wn * 32 + ns * 8 + 2 * t;
            *reinterpret_cast<float2*>(&Ss[(wm * 16 + g) * SQL + col]) =
                make_float2(Sacc[ns][0], Sacc[ns][1]);
            *reinterpret_cast<float2*>(&Ss[(wm * 16 + g + 8) * SQL + col]) =
                make_float2(Sacc[ns][2], Sacc[ns][3]);
        }
        __syncthreads();

        // --- online softmax (4 threads per row, 16 cols each) ---
        {
            const int row = tid >> 2, q = tid & 3;
            float* Sr = &Ss[row * SQL + q * 16];
            float tmax = -3.0e38f;
#pragma unroll
            for (int c = 0; c < 16; c++) tmax = fmaxf(tmax, Sr[c]);
            tmax = fmaxf(tmax, __shfl_xor_sync(0xffffffffu, tmax, 1));
            tmax = fmaxf(tmax, __shfl_xor_sync(0xffffffffu, tmax, 2));
            const float mold = mrow[row];
            const float mnew = fmaxf(mold, tmax);
            float s = 0.f;
#pragma unroll
            for (int c = 0; c < 16; c++) {
                const float p = __expf(Sr[c] - mnew);
                s += p;
                Sr[c] = __uint_as_float(f2tf(p));   // P in tf32 for second MMA
            }
            s += __shfl_xor_sync(0xffffffffu, s, 1);
            s += __shfl_xor_sync(0xffffffffu, s, 2);
            if (q == 0) {
                const float al = __expf(mold - mnew);
                arow[row] = al;
                mrow[row] = mnew;
                lrow[row] = lrow[row] * al + s;
            }
        }
        __syncthreads();

        // --- rescale O and accumulate O += P @ V (warp tile 16 x 64) ---
        {
            const float a0 = arow[wm * 16 + g];
            const float a1 = arow[wm * 16 + g + 8];
#pragma unroll
            for (int ns = 0; ns < 8; ns++) {
                Oacc[ns][0] *= a0; Oacc[ns][1] *= a0;
                Oacc[ns][2] *= a1; Oacc[ns][3] *= a1;
            }
#pragma unroll
            for (int ks = 0; ks < 8; ks++) {
                const int k0 = ks * 8;
                uint32_t a[4];
                const float* Ab = &Ss[(wm * 16) * SQL + k0];
                a[0] = fu(Ab[g * SQL + t]);
                a[1] = fu(Ab[(g + 8) * SQL + t]);
                a[2] = fu(Ab[g * SQL + t + 4]);
                a[3] = fu(Ab[(g + 8) * SQL + t + 4]);
#pragma unroll
                for (int ns = 0; ns < 8; ns++) {
                    const float* Bb = &Vs[(wn * 64 + ns * 8 + g) * SVL + k0];
                    uint32_t b[2] = { fu(Bb[t]), fu(Bb[t + 4]) };
                    mma8(Oacc[ns], a, b);
                }
            }
        }
    }

    __syncthreads();
    // epilogue: divide by softmax denominator, store per-head output
    {
        const float r0 = 1.f / lrow[wm * 16 + g];
        const float r1 = 1.f / lrow[wm * 16 + g + 8];
        float* dst = g_Oh[h] + (size_t)(i0 + wm * 16) * DV + wn * 64;
#pragma unroll
        for (int ns = 0; ns < 8; ns++) {
            const int col = ns * 8 + 2 * t;
            *reinterpret_cast<float2*>(&dst[(size_t)g * DV + col]) =
                make_float2(Oacc[ns][0] * r0, Oacc[ns][1] * r0);
            *reinterpret_cast<float2*>(&dst[(size_t)(g + 8) * DV + col]) =
                make_float2(Oacc[ns][2] * r1, Oacc[ns][3] * r1);
        }
    }
}

// ===========================================================================
// Kernel 3: sum heads + LayerNorm over last dim (128)
// ===========================================================================
__global__ void __launch_bounds__(128) ln_kernel(
    const float* __restrict__ ln_w, const float* __restrict__ ln_b,
    float* __restrict__ out)
{
    const int i = blockIdx.x;
    const int e = threadIdx.x;     // 0..127
    const int lane = e & 31, w = e >> 5;

    float s = 0.f;
#pragma unroll
    for (int h = 0; h < NH; h++) s += g_Oh[h][(size_t)i * DV + e];

    __shared__ float red[4];
    float v = s;
#pragma unroll
    for (int o = 16; o > 0; o >>= 1) v += __shfl_xor_sync(0xffffffffu, v, o);
    if (lane == 0) red[w] = v;
    __syncthreads();
    const float mean = (red[0] + red[1] + red[2] + red[3]) * (1.f / 128.f);
    const float d = s - mean;

    float vv = d * d;
#pragma unroll
    for (int o = 16; o > 0; o >>= 1) vv += __shfl_xor_sync(0xffffffffu, vv, o);
    __syncthreads();
    if (lane == 0) red[w] = vv;
    __syncthreads();
    const float var = (red[0] + red[1] + red[2] + red[3]) * (1.f / 128.f);

    out[(size_t)i * DV + e] = d * rsqrtf(var + 1e-5f) * __ldg(&ln_w[e]) + __ldg(&ln_b[e]);
}

// ===========================================================================
extern "C" void kernel_launch(void* const* d_in, const int* in_sizes, int n_in,
                              void* d_out, int out_size) {
    (void)in_sizes; (void)n_in; (void)out_size;
    const float* x  = (const float*)d_in[0];
    const float* Wk = (const float*)d_in[1];
    const float* bk = (const float*)d_in[2];
    const float* Wq = (const float*)d_in[3];
    const float* bq = (const float*)d_in[4];
    const float* Wv = (const float*)d_in[5];
    const float* bv = (const float*)d_in[6];
    const float* lw = (const float*)d_in[7];
    const float* lb = (const float*)d_in[8];
    float* out = (float*)d_out;

    // projections: grid.y = 8 (Wk) + 8 (Wq) + 16 (Wv) tiles of 64 cols
    proj_kernel<<<dim3(SEQ / PBM, 32), 256>>>(x, Wk, bk, Wq, bq, Wv, bv);

    cudaFuncSetAttribute(attn_kernel, cudaFuncAttributeMaxDynamicSharedMemorySize,
                         ATTN_SMEM_BYTES);
    attn_kernel<<<dim3(SEQ / TI, NH), 256, ATTN_SMEM_BYTES>>>();

    ln_kernel<<<SEQ, 128>>>(lw, lb, out);
}

// round 15
// speedup vs baseline: 1.0194x; 1.0039x over previous
#include <cuda_runtime.h>
#include <cstdint>

#define SEQ 4096
#define DIN 1024
#define NH 8
#define DH 64          // hidden per head
#define DV 128         // NUM_OUT per head
#define DKQ 512        // NH*DH
#define DVA 1024       // NH*DV

// ---------------- scratch (static device allocations are allowed) ----------
static __device__ float g_K[SEQ * DKQ];            // scaled keys-projection (attention "Q")
static __device__ float g_Q[SEQ * DKQ];            // queries-projection (attention "K")
static __device__ float g_V[SEQ * DVA];
static __device__ float g_Oh[NH][SEQ * DV];        // per-head attention outputs

// ---------------- helpers ---------------------------------------------------
__device__ __forceinline__ uint32_t f2tf(float x) {
    uint32_t r;
    asm("cvt.rna.tf32.f32 %0, %1;" : "=r"(r) : "f"(x));
    return r;
}
__device__ __forceinline__ uint32_t fu(float x) { return __float_as_uint(x); }

__device__ __forceinline__ void mma8(float c[4], const uint32_t a[4], const uint32_t b[2]) {
    asm volatile(
        "mma.sync.aligned.m16n8k8.row.col.f32.tf32.tf32.f32 "
        "{%0,%1,%2,%3}, {%4,%5,%6,%7}, {%8,%9}, {%0,%1,%2,%3};\n"
        : "+f"(c[0]), "+f"(c[1]), "+f"(c[2]), "+f"(c[3])
        : "r"(a[0]), "r"(a[1]), "r"(a[2]), "r"(a[3]), "r"(b[0]), "r"(b[1]));
}

// ===========================================================================
// Kernel 1: fused projections  Y = x @ W^T + b  (times scale for K)
//   block tile 128x64, K-tile 32, 256 threads (8 warps, 4x2), tf32 MMA
//   grid.y: 0..7 -> Wk tiles, 8..15 -> Wq tiles, 16..31 -> Wv tiles
// ===========================================================================
#define PBM 128
#define PBN 64
#define PBK 32
#define PLDA 36
#define PNKT (DIN / PBK)   // 32

__global__ void __launch_bounds__(256) proj_kernel(
    const float* __restrict__ x,
    const float* __restrict__ Wk, const float* __restrict__ bk,
    const float* __restrict__ Wq, const float* __restrict__ bq,
    const float* __restrict__ Wv, const float* __restrict__ bv)
{
    __shared__ __align__(16) float As[PBM * PLDA];
    __shared__ __align__(16) float Bs[PBN * PLDA];

    int nt = blockIdx.y;
    const float* W;
    const float* bias;
    float* Y;
    int ncols;
    float scale;
    if (nt < 8)       { W = Wk; bias = bk; Y = g_K; ncols = DKQ; scale = 0.125f; }
    else if (nt < 16) { W = Wq; bias = bq; Y = g_Q; ncols = DKQ; scale = 1.0f; nt -= 8; }
    else              { W = Wv; bias = bv; Y = g_V; ncols = DVA; scale = 1.0f; nt -= 16; }
    const int n0 = nt * PBN;
    const int m0 = blockIdx.x * PBM;

    const int tid = threadIdx.x, lane = tid & 31, warp = tid >> 5;
    const int g = lane >> 2, t = lane & 3;
    const int wm = warp & 3, wn = warp >> 2;   // warp tile: rows wm*32, cols wn*32

    const int lr  = tid >> 3;   // loader row 0..31
    const int lc4 = tid & 7;    // loader float4 col 0..7

    const float* xp = x + (size_t)(m0 + lr) * DIN + lc4 * 4;
    const float* wp = W + (size_t)(n0 + lr) * DIN + lc4 * 4;

    float4 xa[4];
    float4 wa[2];
    float acc[2][4][4];
#pragma unroll
    for (int i = 0; i < 2; i++)
#pragma unroll
        for (int j = 0; j < 4; j++)
#pragma unroll
            for (int k = 0; k < 4; k++) acc[i][j][k] = 0.f;

    // prologue load + store
#pragma unroll
    for (int r = 0; r < 4; r++) xa[r] = *(const float4*)(xp + (size_t)r * 32 * DIN);
#pragma unroll
    for (int r = 0; r < 2; r++) wa[r] = *(const float4*)(wp + (size_t)r * 32 * DIN);
#pragma unroll
    for (int r = 0; r < 4; r++) {
        uint4 u4;
        u4.x = f2tf(xa[r].x); u4.y = f2tf(xa[r].y); u4.z = f2tf(xa[r].z); u4.w = f2tf(xa[r].w);
        *reinterpret_cast<uint4*>(&As[(lr + r * 32) * PLDA + lc4 * 4]) = u4;
    }
#pragma unroll
    for (int r = 0; r < 2; r++) {
        uint4 u4;
        u4.x = f2tf(wa[r].x); u4.y = f2tf(wa[r].y); u4.z = f2tf(wa[r].z); u4.w = f2tf(wa[r].w);
        *reinterpret_cast<uint4*>(&Bs[(lr + r * 32) * PLDA + lc4 * 4]) = u4;
    }
    __syncthreads();

    for (int kt = 0; kt < PNKT; kt++) {
        const int knext = (kt + 1) * PBK;
        if (kt + 1 < PNKT) {
#pragma unroll
            for (int r = 0; r < 4; r++) xa[r] = *(const float4*)(xp + (size_t)r * 32 * DIN + knext);
#pragma unroll
            for (int r = 0; r < 2; r++) wa[r] = *(const float4*)(wp + (size_t)r * 32 * DIN + knext);
        }
        // compute from smem
#pragma unroll
        for (int ks = 0; ks < 4; ks++) {
            const int k0 = ks * 8;
            uint32_t afr[2][4];
#pragma unroll
            for (int ms = 0; ms < 2; ms++) {
                const float* Ab = &As[(wm * 32 + ms * 16) * PLDA + k0];
                afr[ms][0] = fu(Ab[g * PLDA + t]);
                afr[ms][1] = fu(Ab[(g + 8) * PLDA + t]);
                afr[ms][2] = fu(Ab[g * PLDA + t + 4]);
                afr[ms][3] = fu(Ab[(g + 8) * PLDA + t + 4]);
            }
#pragma unroll
            for (int ns = 0; ns < 4; ns++) {
                const float* Bb = &Bs[(wn * 32 + ns * 8 + g) * PLDA + k0];
                uint32_t bfr[2];
                bfr[0] = fu(Bb[t]);
                bfr[1] = fu(Bb[t + 4]);
#pragma unroll
                for (int ms = 0; ms < 2; ms++) mma8(acc[ms][ns], afr[ms], bfr);
            }
        }
        __syncthreads();
        if (kt + 1 < PNKT) {
#pragma unroll
            for (int r = 0; r < 4; r++) {
                uint4 u4;
                u4.x = f2tf(xa[r].x); u4.y = f2tf(xa[r].y); u4.z = f2tf(xa[r].z); u4.w = f2tf(xa[r].w);
                *reinterpret_cast<uint4*>(&As[(lr + r * 32) * PLDA + lc4 * 4]) = u4;
            }
#pragma unroll
            for (int r = 0; r < 2; r++) {
                uint4 u4;
                u4.x = f2tf(wa[r].x); u4.y = f2tf(wa[r].y); u4.z = f2tf(wa[r].z); u4.w = f2tf(wa[r].w);
                *reinterpret_cast<uint4*>(&Bs[(lr + r * 32) * PLDA + lc4 * 4]) = u4;
            }
            __syncthreads();
        }
    }

    // epilogue: bias + scale
#pragma unroll
    for (int ms = 0; ms < 2; ms++) {
        const int row = m0 + wm * 32 + ms * 16;
#pragma unroll
        for (int ns = 0; ns < 4; ns++) {
            const int col = n0 + wn * 32 + ns * 8 + 2 * t;
            const float b0 = __ldg(&bias[col]);
            const float b1 = __ldg(&bias[col + 1]);
            float2 v0 = make_float2((acc[ms][ns][0] + b0) * scale, (acc[ms][ns][1] + b1) * scale);
            float2 v1 = make_float2((acc[ms][ns][2] + b0) * scale, (acc[ms][ns][3] + b1) * scale);
            *reinterpret_cast<float2*>(&Y[(size_t)(row + g) * ncols + col]) = v0;
            *reinterpret_cast<float2*>(&Y[(size_t)(row + g + 8) * ncols + col]) = v1;
        }
    }
}

// ===========================================================================
// Kernel 2: flash attention per (i-tile of 64, head)
//   attention Q := g_K rows (already scaled), K := g_Q rows, V := g_V
//   8 warps in 4(M) x 2(N); online softmax over j; tf32 MMAs, fp32 stats
// ===========================================================================
#define TI 64
#define TJ 64
#define SQL 68   // smem row stride for Qs/Ks/Ss
#define SVL 68   // smem row stride for Vs (transposed [e][j])

static constexpr int ATTN_SMEM_FLOATS = 64 * SQL * 3 + 128 * SVL + 192;
static constexpr int ATTN_SMEM_BYTES  = ATTN_SMEM_FLOATS * 4;   // 87808 B

__global__ void __launch_bounds__(256, 2) attn_kernel() {
    extern __shared__ __align__(16) float sm[];
    float* Qs   = sm;                    // [64][SQL] tf32
    float* Ks   = Qs + 64 * SQL;         // [64][SQL] tf32
    float* Ss   = Ks + 64 * SQL;         // [64][SQL] fp32 scores -> tf32 P
    float* Vs   = Ss + 64 * SQL;         // [128][SVL] tf32, transposed (e, j)
    float* mrow = Vs + 128 * SVL;        // [64]
    float* lrow = mrow + 64;             // [64]
    float* arow = lrow + 64;             // [64]

    const int h  = blockIdx.y;
    const int i0 = blockIdx.x * TI;
    const int tid = threadIdx.x, lane = tid & 31, warp = tid >> 5;
    const int g = lane >> 2, t = lane & 3;
    const int wm = warp & 3, wn = warp >> 2;

    // load Q' tile once (rows i0.., head h), convert to tf32
    {
        const float* src = g_K + (size_t)i0 * DKQ + h * DH;
        for (int idx = tid; idx < 64 * 16; idx += 256) {
            const int r = idx >> 4, c4 = idx & 15;
            float4 v = *(const float4*)(src + (size_t)r * DKQ + c4 * 4);
            uint4 u4;
            u4.x = f2tf(v.x); u4.y = f2tf(v.y); u4.z = f2tf(v.z); u4.w = f2tf(v.w);
            *reinterpret_cast<uint4*>(&Qs[r * SQL + c4 * 4]) = u4;
        }
    }
    if (tid < 64) { mrow[tid] = -3.0e38f; lrow[tid] = 0.f; }

    float Oacc[8][4];
#pragma unroll
    for (int i = 0; i < 8; i++)
#pragma unroll
        for (int j = 0; j < 4; j++) Oacc[i][j] = 0.f;

    for (int jt = 0; jt < SEQ / TJ; ++jt) {
        __syncthreads();   // previous iteration fully done with Ks/Vs/Ss
        // load K' tile (g_Q) -> Ks, tf32
        {
            const float* src = g_Q + (size_t)(jt * TJ) * DKQ + h * DH;
            for (int idx = tid; idx < 64 * 16; idx += 256) {
                const int r = idx >> 4, c4 = idx & 15;
                float4 v = *(const float4*)(src + (size_t)r * DKQ + c4 * 4);
                uint4 u4;
                u4.x = f2tf(v.x); u4.y = f2tf(v.y); u4.z = f2tf(v.z); u4.w = f2tf(v.w);
                *reinterpret_cast<uint4*>(&Ks[r * SQL + c4 * 4]) = u4;
            }
        }
        // load V tile transposed -> Vs[e][j], tf32
        {
            const float* src = g_V + (size_t)(jt * TJ) * DVA + h * DV;
            for (int idx = tid; idx < 64 * 128; idx += 256) {
                const int j = idx >> 7, e = idx & 127;
                Vs[e * SVL + j] = __uint_as_float(f2tf(src[(size_t)j * DVA + e]));
            }
        }
        __syncthreads();

        // --- S = Q' K'^T  (warp tile 16 x 32) ---
        float Sacc[4][4];
#pragma unroll
        for (int i = 0; i < 4; i++)
#pragma unroll
            for (int j = 0; j < 4; j++) Sacc[i][j] = 0.f;
#pragma unroll
        for (int ks = 0; ks < 8; ks++) {
            const int k0 = ks * 8;
            uint32_t a[4];
            const float* Ab = &Qs[(wm * 16) * SQL + k0];
            a[0] = fu(Ab[g * SQL + t]);
            a[1] = fu(Ab[(g + 8) * SQL + t]);
            a[2] = fu(Ab[g * SQL + t + 4]);
            a[3] = fu(Ab[(g + 8) * SQL + t + 4]);
#pragma unroll
            for (int ns = 0; ns < 4; ns++) {
                const float* Bb = &Ks[(wn * 32 + ns * 8 + g) * SQL + k0];
                uint32_t b[2] = { fu(Bb[t]), fu(Bb[t + 4]) };
                mma8(Sacc[ns], a, b);
            }
        }
        // write scores to smem
#pragma unroll
        for (int ns = 0; ns < 4; ns++) {
            const int col = wn * 32 + ns * 8 + 2 * t;
            *reinterpret_cast<float2*>(&Ss[(wm * 16 + g) * SQL + col]) =
                make_float2(Sacc[ns][0], Sacc[ns][1]);
            *reinterpret_cast<float2*>(&Ss[(wm * 16 + g + 8) * SQL + col]) =
                make_float2(Sacc[ns][2], Sacc[ns][3]);
        }
        __syncthreads();

        // --- online softmax (4 threads per row, 16 cols each) ---
        {
            const int row = tid >> 2, q = tid & 3;
            float* Sr = &Ss[row * SQL + q * 16];
            float tmax = -3.0e38f;
#pragma unroll
            for (int c = 0; c < 16; c++) tmax = fmaxf(tmax, Sr[c]);
            tmax = fmaxf(tmax, __shfl_xor_sync(0xffffffffu, tmax, 1));
            tmax = fmaxf(tmax, __shfl_xor_sync(0xffffffffu, tmax, 2));
            const float mold = mrow[row];
            const float mnew = fmaxf(mold, tmax);
            float s = 0.f;
#pragma unroll
            for (int c = 0; c < 16; c++) {
                const float p = __expf(Sr[c] - mnew);
                s += p;
                Sr[c] = __uint_as_float(f2tf(p));   // P in tf32 for second MMA
            }
            s += __shfl_xor_sync(0xffffffffu, s, 1);
            s += __shfl_xor_sync(0xffffffffu, s, 2);
            if (q == 0) {
                const float al = __expf(mold - mnew);
                arow[row] = al;
                mrow[row] = mnew;
                lrow[row] = lrow[row] * al + s;
            }
        }
        __syncthreads();

        // --- rescale O and accumulate O += P @ V (warp tile 16 x 64) ---
        {
            const float a0 = arow[wm * 16 + g];
            const float a1 = arow[wm * 16 + g + 8];
#pragma unroll
            for (int ns = 0; ns < 8; ns++) {
                Oacc[ns][0] *= a0; Oacc[ns][1] *= a0;
                Oacc[ns][2] *= a1; Oacc[ns][3] *= a1;
            }
#pragma unroll
            for (int ks = 0; ks < 8; ks++) {
                const int k0 = ks * 8;
                uint32_t a[4];
                const float* Ab = &Ss[(wm * 16) * SQL + k0];
                a[0] = fu(Ab[g * SQL + t]);
                a[1] = fu(Ab[(g + 8) * SQL + t]);
                a[2] = fu(Ab[g * SQL + t + 4]);
                a[3] = fu(Ab[(g + 8) * SQL + t + 4]);
#pragma unroll
                for (int ns = 0; ns < 8; ns++) {
                    const float* Bb = &Vs[(wn * 64 + ns * 8 + g) * SVL + k0];
                    uint32_t b[2] = { fu(Bb[t]), fu(Bb[t + 4]) };
                    mma8(Oacc[ns], a, b);
                }
            }
        }
    }

    __syncthreads();
    // epilogue: divide by softmax denominator, store per-head output
    {
        const float r0 = 1.f / lrow[wm * 16 + g];
        const float r1 = 1.f / lrow[wm * 16 + g + 8];
        float* dst = g_Oh[h] + (size_t)(i0 + wm * 16) * DV + wn * 64;
#pragma unroll
        for (int ns = 0; ns < 8; ns++) {
            const int col = ns * 8 + 2 * t;
            *reinterpret_cast<float2*>(&dst[(size_t)g * DV + col]) =
                make_float2(Oacc[ns][0] * r0, Oacc[ns][1] * r0);
            *reinterpret_cast<float2*>(&dst[(size_t)(g + 8) * DV + col]) =
                make_float2(Oacc[ns][2] * r1, Oacc[ns][3] * r1);
        }
    }
}

// ===========================================================================
// Kernel 3: sum heads + LayerNorm over last dim (128)
// ===========================================================================
__global__ void __launch_bounds__(128) ln_kernel(
    const float* __restrict__ ln_w, const float* __restrict__ ln_b,
    float* __restrict__ out)
{
    const int i = blockIdx.x;
    const int e = threadIdx.x;     // 0..127
    const int lane = e & 31, w = e >> 5;

    float s = 0.f;
#pragma unroll
    for (int h = 0; h < NH; h++) s += g_Oh[h][(size_t)i * DV + e];

    __shared__ float red[4];
    float v = s;
#pragma unroll
    for (int o = 16; o > 0; o >>= 1) v += __shfl_xor_sync(0xffffffffu, v, o);
    if (lane == 0) red[w] = v;
    __syncthreads();
    const float mean = (red[0] + red[1] + red[2] + red[3]) * (1.f / 128.f);
    const float d = s - mean;

    float vv = d * d;
#pragma unroll
    for (int o = 16; o > 0; o >>= 1) vv += __shfl_xor_sync(0xffffffffu, vv, o);
    __syncthreads();
    if (lane == 0) red[w] = vv;
    __syncthreads();
    const float var = (red[0] + red[1] + red[2] + red[3]) * (1.f / 128.f);

    out[(size_t)i * DV + e] = d * rsqrtf(var + 1e-5f) * __ldg(&ln_w[e]) + __ldg(&ln_b[e]);
}

// ===========================================================================
extern "C" void kernel_launch(void* const* d_in, const int* in_sizes, int n_in,
                              void* d_out, int out_size) {
    (void)in_sizes; (void)n_in; (void)out_size;
    const float* x  = (const float*)d_in[0];
    const float* Wk = (const float*)d_in[1];
    const float* bk = (const float*)d_in[2];
    const float* Wq = (const float*)d_in[3];
    const float* bq = (const float*)d_in[4];
    const float* Wv = (const float*)d_in[5];
    const float* bv = (const float*)d_in[6];
    const float* lw = (const float*)d_in[7];
    const float* lb = (const float*)d_in[8];
    float* out = (float*)d_out;

    // projections: grid.y = 8 (Wk) + 8 (Wq) + 16 (Wv) tiles of 64 cols
    proj_kernel<<<dim3(SEQ / PBM, 32), 256>>>(x, Wk, bk, Wq, bq, Wv, bv);

    cudaFuncSetAttribute(attn_kernel, cudaFuncAttributeMaxDynamicSharedMemorySize,
                         ATTN_SMEM_BYTES);
    attn_kernel<<<dim3(SEQ / TI, NH), 256, ATTN_SMEM_BYTES>>>();

    ln_kernel<<<SEQ, 128>>>(lw, lb, out);
}

// round 16
// speedup vs baseline: 1.0289x; 1.0093x over previous
#include <cuda_runtime.h>
#include <cstdint>

#define SEQ 4096
#define DIN 1024
#define NH 8
#define DH 64          // hidden per head
#define DV 128         // NUM_OUT per head
#define DKQ 512        // NH*DH
#define DVA 1024       // NH*DV

// ---------------- scratch (static device allocations are allowed) ----------
static __device__ float g_K[SEQ * DKQ];            // scaled keys-projection (attention "Q")
static __device__ float g_Q[SEQ * DKQ];            // queries-projection (attention "K")
static __device__ float g_V[SEQ * DVA];
static __device__ float g_Oh[NH][SEQ * DV];        // per-head attention outputs

// ---------------- helpers ---------------------------------------------------
__device__ __forceinline__ uint32_t f2tf(float x) {
    uint32_t r;
    asm("cvt.rna.tf32.f32 %0, %1;" : "=r"(r) : "f"(x));
    return r;
}
__device__ __forceinline__ uint32_t fu(float x) { return __float_as_uint(x); }

__device__ __forceinline__ void mma8(float c[4], const uint32_t a[4], const uint32_t b[2]) {
    asm volatile(
        "mma.sync.aligned.m16n8k8.row.col.f32.tf32.tf32.f32 "
        "{%0,%1,%2,%3}, {%4,%5,%6,%7}, {%8,%9}, {%0,%1,%2,%3};\n"
        : "+f"(c[0]), "+f"(c[1]), "+f"(c[2]), "+f"(c[3])
        : "r"(a[0]), "r"(a[1]), "r"(a[2]), "r"(a[3]), "r"(b[0]), "r"(b[1]));
}

// ===========================================================================
// Kernel 1: fused projections  Y = x @ W^T + b  (times scale for K)
//   block tile 128x64, K-tile 32, 256 threads (8 warps, 4x2), tf32 MMA
//   grid.y: 0..7 -> Wk tiles, 8..15 -> Wq tiles, 16..31 -> Wv tiles
// ===========================================================================
#define PBM 128
#define PBN 64
#define PBK 32
#define PLDA 36
#define PNKT (DIN / PBK)   // 32

__global__ void __launch_bounds__(256) proj_kernel(
    const float* __restrict__ x,
    const float* __restrict__ Wk, const float* __restrict__ bk,
    const float* __restrict__ Wq, const float* __restrict__ bq,
    const float* __restrict__ Wv, const float* __restrict__ bv)
{
    __shared__ __align__(16) float As[PBM * PLDA];
    __shared__ __align__(16) float Bs[PBN * PLDA];

    int nt = blockIdx.y;
    const float* W;
    const float* bias;
    float* Y;
    int ncols;
    float scale;
    if (nt < 8)       { W = Wk; bias = bk; Y = g_K; ncols = DKQ; scale = 0.125f; }
    else if (nt < 16) { W = Wq; bias = bq; Y = g_Q; ncols = DKQ; scale = 1.0f; nt -= 8; }
    else              { W = Wv; bias = bv; Y = g_V; ncols = DVA; scale = 1.0f; nt -= 16; }
    const int n0 = nt * PBN;
    const int m0 = blockIdx.x * PBM;

    const int tid = threadIdx.x, lane = tid & 31, warp = tid >> 5;
    const int g = lane >> 2, t = lane & 3;
    const int wm = warp & 3, wn = warp >> 2;   // warp tile: rows wm*32, cols wn*32

    const int lr  = tid >> 3;   // loader row 0..31
    const int lc4 = tid & 7;    // loader float4 col 0..7

    const float* xp = x + (size_t)(m0 + lr) * DIN + lc4 * 4;
    const float* wp = W + (size_t)(n0 + lr) * DIN + lc4 * 4;

    float4 xa[4];
    float4 wa[2];
    float acc[2][4][4];
#pragma unroll
    for (int i = 0; i < 2; i++)
#pragma unroll
        for (int j = 0; j < 4; j++)
#pragma unroll
            for (int k = 0; k < 4; k++) acc[i][j][k] = 0.f;

    // prologue load + store
#pragma unroll
    for (int r = 0; r < 4; r++) xa[r] = *(const float4*)(xp + (size_t)r * 32 * DIN);
#pragma unroll
    for (int r = 0; r < 2; r++) wa[r] = *(const float4*)(wp + (size_t)r * 32 * DIN);
#pragma unroll
    for (int r = 0; r < 4; r++) {
        uint4 u4;
        u4.x = f2tf(xa[r].x); u4.y = f2tf(xa[r].y); u4.z = f2tf(xa[r].z); u4.w = f2tf(xa[r].w);
        *reinterpret_cast<uint4*>(&As[(lr + r * 32) * PLDA + lc4 * 4]) = u4;
    }
#pragma unroll
    for (int r = 0; r < 2; r++) {
        uint4 u4;
        u4.x = f2tf(wa[r].x); u4.y = f2tf(wa[r].y); u4.z = f2tf(wa[r].z); u4.w = f2tf(wa[r].w);
        *reinterpret_cast<uint4*>(&Bs[(lr + r * 32) * PLDA + lc4 * 4]) = u4;
    }
    __syncthreads();

    for (int kt = 0; kt < PNKT; kt++) {
        const int knext = (kt + 1) * PBK;
        if (kt + 1 < PNKT) {
#pragma unroll
            for (int r = 0; r < 4; r++) xa[r] = *(const float4*)(xp + (size_t)r * 32 * DIN + knext);
#pragma unroll
            for (int r = 0; r < 2; r++) wa[r] = *(const float4*)(wp + (size_t)r * 32 * DIN + knext);
        }
        // compute from smem
#pragma unroll
        for (int ks = 0; ks < 4; ks++) {
            const int k0 = ks * 8;
            uint32_t afr[2][4];
#pragma unroll
            for (int ms = 0; ms < 2; ms++) {
                const float* Ab = &As[(wm * 32 + ms * 16) * PLDA + k0];
                afr[ms][0] = fu(Ab[g * PLDA + t]);
                afr[ms][1] = fu(Ab[(g + 8) * PLDA + t]);
                afr[ms][2] = fu(Ab[g * PLDA + t + 4]);
                afr[ms][3] = fu(Ab[(g + 8) * PLDA + t + 4]);
            }
#pragma unroll
            for (int ns = 0; ns < 4; ns++) {
                const float* Bb = &Bs[(wn * 32 + ns * 8 + g) * PLDA + k0];
                uint32_t bfr[2];
                bfr[0] = fu(Bb[t]);
                bfr[1] = fu(Bb[t + 4]);
#pragma unroll
                for (int ms = 0; ms < 2; ms++) mma8(acc[ms][ns], afr[ms], bfr);
            }
        }
        __syncthreads();
        if (kt + 1 < PNKT) {
#pragma unroll
            for (int r = 0; r < 4; r++) {
                uint4 u4;
                u4.x = f2tf(xa[r].x); u4.y = f2tf(xa[r].y); u4.z = f2tf(xa[r].z); u4.w = f2tf(xa[r].w);
                *reinterpret_cast<uint4*>(&As[(lr + r * 32) * PLDA + lc4 * 4]) = u4;
            }
#pragma unroll
            for (int r = 0; r < 2; r++) {
                uint4 u4;
                u4.x = f2tf(wa[r].x); u4.y = f2tf(wa[r].y); u4.z = f2tf(wa[r].z); u4.w = f2tf(wa[r].w);
                *reinterpret_cast<uint4*>(&Bs[(lr + r * 32) * PLDA + lc4 * 4]) = u4;
            }
            __syncthreads();
        }
    }

    // epilogue: bias + scale
#pragma unroll
    for (int ms = 0; ms < 2; ms++) {
        const int row = m0 + wm * 32 + ms * 16;
#pragma unroll
        for (int ns = 0; ns < 4; ns++) {
            const int col = n0 + wn * 32 + ns * 8 + 2 * t;
            const float b0 = __ldg(&bias[col]);
            const float b1 = __ldg(&bias[col + 1]);
            float2 v0 = make_float2((acc[ms][ns][0] + b0) * scale, (acc[ms][ns][1] + b1) * scale);
            float2 v1 = make_float2((acc[ms][ns][2] + b0) * scale, (acc[ms][ns][3] + b1) * scale);
            *reinterpret_cast<float2*>(&Y[(size_t)(row + g) * ncols + col]) = v0;
            *reinterpret_cast<float2*>(&Y[(size_t)(row + g + 8) * ncols + col]) = v1;
        }
    }
}

// ===========================================================================
// Kernel 2: flash attention per (i-tile of 64, head)
//   attention Q := g_K rows (already scaled), K := g_Q rows, V := g_V
//   8 warps in 4(M) x 2(N); online softmax over j; tf32 MMAs, fp32 stats
// ===========================================================================
#define TI 64
#define TJ 64
#define SQL 68   // smem row stride for Qs/Ks/Ss
#define SVL 68   // smem row stride for Vs (transposed [e][j])

static constexpr int ATTN_SMEM_FLOATS = 64 * SQL * 3 + 128 * SVL + 192;
static constexpr int ATTN_SMEM_BYTES  = ATTN_SMEM_FLOATS * 4;   // 87808 B

__global__ void __launch_bounds__(256, 2) attn_kernel() {
    extern __shared__ __align__(16) float sm[];
    float* Qs   = sm;                    // [64][SQL] tf32
    float* Ks   = Qs + 64 * SQL;         // [64][SQL] tf32
    float* Ss   = Ks + 64 * SQL;         // [64][SQL] fp32 scores -> tf32 P
    float* Vs   = Ss + 64 * SQL;         // [128][SVL] tf32, transposed (e, j)
    float* mrow = Vs + 128 * SVL;        // [64]
    float* lrow = mrow + 64;             // [64]
    float* arow = lrow + 64;             // [64]

    const int h  = blockIdx.y;
    const int i0 = blockIdx.x * TI;
    const int tid = threadIdx.x, lane = tid & 31, warp = tid >> 5;
    const int g = lane >> 2, t = lane & 3;
    const int wm = warp & 3, wn = warp >> 2;

    // load Q' tile once (rows i0.., head h), convert to tf32
    {
        const float* src = g_K + (size_t)i0 * DKQ + h * DH;
        for (int idx = tid; idx < 64 * 16; idx += 256) {
            const int r = idx >> 4, c4 = idx & 15;
            float4 v = *(const float4*)(src + (size_t)r * DKQ + c4 * 4);
            uint4 u4;
            u4.x = f2tf(v.x); u4.y = f2tf(v.y); u4.z = f2tf(v.z); u4.w = f2tf(v.w);
            *reinterpret_cast<uint4*>(&Qs[r * SQL + c4 * 4]) = u4;
        }
    }
    if (tid < 64) { mrow[tid] = -3.0e38f; lrow[tid] = 0.f; }

    float Oacc[8][4];
#pragma unroll
    for (int i = 0; i < 8; i++)
#pragma unroll
        for (int j = 0; j < 4; j++) Oacc[i][j] = 0.f;

    for (int jt = 0; jt < SEQ / TJ; ++jt) {
        __syncthreads();   // previous iteration fully done with Ks/Vs/Ss
        // load K' tile (g_Q) -> Ks, tf32
        {
            const float* src = g_Q + (size_t)(jt * TJ) * DKQ + h * DH;
            for (int idx = tid; idx < 64 * 16; idx += 256) {
                const int r = idx >> 4, c4 = idx & 15;
                float4 v = *(const float4*)(src + (size_t)r * DKQ + c4 * 4);
                uint4 u4;
                u4.x = f2tf(v.x); u4.y = f2tf(v.y); u4.z = f2tf(v.z); u4.w = f2tf(v.w);
                *reinterpret_cast<uint4*>(&Ks[r * SQL + c4 * 4]) = u4;
            }
        }
        // load V tile transposed -> Vs[e][j], tf32
        {
            const float* src = g_V + (size_t)(jt * TJ) * DVA + h * DV;
            for (int idx = tid; idx < 64 * 128; idx += 256) {
                const int j = idx >> 7, e = idx & 127;
                Vs[e * SVL + j] = __uint_as_float(f2tf(src[(size_t)j * DVA + e]));
            }
        }
        __syncthreads();

        // --- S = Q' K'^T  (warp tile 16 x 32) ---
        float Sacc[4][4];
#pragma unroll
        for (int i = 0; i < 4; i++)
#pragma unroll
            for (int j = 0; j < 4; j++) Sacc[i][j] = 0.f;
#pragma unroll
        for (int ks = 0; ks < 8; ks++) {
            const int k0 = ks * 8;
            uint32_t a[4];
            const float* Ab = &Qs[(wm * 16) * SQL + k0];
            a[0] = fu(Ab[g * SQL + t]);
            a[1] = fu(Ab[(g + 8) * SQL + t]);
            a[2] = fu(Ab[g * SQL + t + 4]);
            a[3] = fu(Ab[(g + 8) * SQL + t + 4]);
#pragma unroll
            for (int ns = 0; ns < 4; ns++) {
                const float* Bb = &Ks[(wn * 32 + ns * 8 + g) * SQL + k0];
                uint32_t b[2] = { fu(Bb[t]), fu(Bb[t + 4]) };
                mma8(Sacc[ns], a, b);
            }
        }
        // write scores to smem
#pragma unroll
        for (int ns = 0; ns < 4; ns++) {
            const int col = wn * 32 + ns * 8 + 2 * t;
            *reinterpret_cast<float2*>(&Ss[(wm * 16 + g) * SQL + col]) =
                make_float2(Sacc[ns][0], Sacc[ns][1]);
            *reinterpret_cast<float2*>(&Ss[(wm * 16 + g + 8) * SQL + col]) =
                make_float2(Sacc[ns][2], Sacc[ns][3]);
        }
        __syncthreads();

        // --- online softmax (4 threads per row, 16 cols each) ---
        {
            const int row = tid >> 2, q = tid & 3;
            float* Sr = &Ss[row * SQL + q * 16];
            float tmax = -3.0e38f;
#pragma unroll
            for (int c = 0; c < 16; c++) tmax = fmaxf(tmax, Sr[c]);
            tmax = fmaxf(tmax, __shfl_xor_sync(0xffffffffu, tmax, 1));
            tmax = fmaxf(tmax, __shfl_xor_sync(0xffffffffu, tmax, 2));
            const float mold = mrow[row];
            const float mnew = fmaxf(mold, tmax);
            float s = 0.f;
#pragma unroll
            for (int c = 0; c < 16; c++) {
                const float p = __expf(Sr[c] - mnew);
                s += p;
                Sr[c] = __uint_as_float(f2tf(p));   // P in tf32 for second MMA
            }
            s += __shfl_xor_sync(0xffffffffu, s, 1);
            s += __shfl_xor_sync(0xffffffffu, s, 2);
            if (q == 0) {
                const float al = __expf(mold - mnew);
                arow[row] = al;
                mrow[row] = mnew;
                lrow[row] = lrow[row] * al + s;
            }
        }
        __syncthreads();

        // --- rescale O and accumulate O += P @ V (warp tile 16 x 64) ---
        {
            const float a0 = arow[wm * 16 + g];
            const float a1 = arow[wm * 16 + g + 8];
#pragma unroll
            for (int ns = 0; ns < 8; ns++) {
                Oacc[ns][0] *= a0; Oacc[ns][1] *= a0;
                Oacc[ns][2] *= a1; Oacc[ns][3] *= a1;
            }
#pragma unroll
            for (int ks = 0; ks < 8; ks++) {
                const int k0 = ks * 8;
                uint32_t a[4];
                const float* Ab = &Ss[(wm * 16) * SQL + k0];
                a[0] = fu(Ab[g * SQL + t]);
                a[1] = fu(Ab[(g + 8) * SQL + t]);
                a[2] = fu(Ab[g * SQL + t + 4]);
                a[3] = fu(Ab[(g + 8) * SQL + t + 4]);
#pragma unroll
                for (int ns = 0; ns < 8; ns++) {
                    const float* Bb = &Vs[(wn * 64 + ns * 8 + g) * SVL + k0];
                    uint32_t b[2] = { fu(Bb[t]), fu(Bb[t + 4]) };
                    mma8(Oacc[ns], a, b);
                }
            }
        }
    }

    __syncthreads();
    // epilogue: divide by softmax denominator, store per-head output
    {
        const float r0 = 1.f / lrow[wm * 16 + g];
        const float r1 = 1.f / lrow[wm * 16 + g + 8];
        float* dst = g_Oh[h] + (size_t)(i0 + wm * 16) * DV + wn * 64;
#pragma unroll
        for (int ns = 0; ns < 8; ns++) {
            const int col = ns * 8 + 2 * t;
            *reinterpret_cast<float2*>(&dst[(size_t)g * DV + col]) =
                make_float2(Oacc[ns][0] * r0, Oacc[ns][1] * r0);
            *reinterpret_cast<float2*>(&dst[(size_t)(g + 8) * DV + col]) =
                make_float2(Oacc[ns][2] * r1, Oacc[ns][3] * r1);
        }
    }
}

// ===========================================================================
// Kernel 3: sum heads + LayerNorm over last dim (128)
// ===========================================================================
__global__ void __launch_bounds__(128) ln_kernel(
    const float* __restrict__ ln_w, const float* __restrict__ ln_b,
    float* __restrict__ out)
{
    const int i = blockIdx.x;
    const int e = threadIdx.x;     // 0..127
    const int lane = e & 31, w = e >> 5;

    float s = 0.f;
#pragma unroll
    for (int h = 0; h < NH; h++) s += g_Oh[h][(size_t)i * DV + e];

    __shared__ float red[4];
    float v = s;
#pragma unroll
    for (int o = 16; o > 0; o >>= 1) v += __shfl_xor_sync(0xffffffffu, v, o);
    if (lane == 0) red[w] = v;
    __syncthreads();
    const float mean = (red[0] + red[1] + red[2] + red[3]) * (1.f / 128.f);
    const float d = s - mean;

    float vv = d * d;
#pragma unroll
    for (int o = 16; o > 0; o >>= 1) vv += __shfl_xor_sync(0xffffffffu, vv, o);
    __syncthreads();
    if (lane == 0) red[w] = vv;
    __syncthreads();
    const float var = (red[0] + red[1] + red[2] + red[3]) * (1.f / 128.f);

    out[(size_t)i * DV + e] = d * rsqrtf(var + 1e-5f) * __ldg(&ln_w[e]) + __ldg(&ln_b[e]);
}

// ===========================================================================
extern "C" void kernel_launch(void* const* d_in, const int* in_sizes, int n_in,
                              void* d_out, int out_size) {
    (void)in_sizes; (void)n_in; (void)out_size;
    const float* x  = (const float*)d_in[0];
    const float* Wk = (const float*)d_in[1];
    const float* bk = (const float*)d_in[2];
    const float* Wq = (const float*)d_in[3];
    const float* bq = (const float*)d_in[4];
    const float* Wv = (const float*)d_in[5];
    const float* bv = (const float*)d_in[6];
    const float* lw = (const float*)d_in[7];
    const float* lb = (const float*)d_in[8];
    float* out = (float*)d_out;

    // projections: grid.y = 8 (Wk) + 8 (Wq) + 16 (Wv) tiles of 64 cols
    proj_kernel<<<dim3(SEQ / PBM, 32), 256>>>(x, Wk, bk, Wq, bq, Wv, bv);

    cudaFuncSetAttribute(attn_kernel, cudaFuncAttributeMaxDynamicSharedMemorySize,
                         ATTN_SMEM_BYTES);
    attn_kernel<<<dim3(SEQ / TI, NH), 256, ATTN_SMEM_BYTES>>>();

    ln_kernel<<<SEQ, 128>>>(lw, lb, out);
}

// round 17
// speedup vs baseline: 1.8418x; 1.7901x over previous
#include <cuda_runtime.h>
#include <cstdint>

#define SEQ 4096
#define DIN 1024
#define NH 8
#define DH 64          // hidden per head
#define DV 128         // NUM_OUT per head
#define DKQ 512        // NH*DH
#define DVA 1024       // NH*DV

// ---------------- scratch (static device allocations are allowed) ----------
static __device__ float g_K[SEQ * DKQ];            // scaled keys-projection (attention "Q"), tf32-rounded
static __device__ float g_Q[SEQ * DKQ];            // queries-projection (attention "K"), tf32-rounded
static __device__ float g_V[SEQ * DVA];            // tf32-rounded
static __device__ float g_Oh[NH][SEQ * DV];        // per-head attention outputs

// ---------------- helpers ---------------------------------------------------
__device__ __forceinline__ uint32_t f2tf(float x) {
    uint32_t r;
    asm("cvt.rna.tf32.f32 %0, %1;" : "=r"(r) : "f"(x));
    return r;
}
__device__ __forceinline__ uint32_t fu(float x) { return __float_as_uint(x); }

__device__ __forceinline__ void mma8(float c[4], const uint32_t a[4], const uint32_t b[2]) {
    asm volatile(
        "mma.sync.aligned.m16n8k8.row.col.f32.tf32.tf32.f32 "
        "{%0,%1,%2,%3}, {%4,%5,%6,%7}, {%8,%9}, {%0,%1,%2,%3};\n"
        : "+f"(c[0]), "+f"(c[1]), "+f"(c[2]), "+f"(c[3])
        : "r"(a[0]), "r"(a[1]), "r"(a[2]), "r"(a[3]), "r"(b[0]), "r"(b[1]));
}

__device__ __forceinline__ void cp16(uint32_t s, const void* g) {
    asm volatile("cp.async.cg.shared.global [%0], [%1], 16;\n" :: "r"(s), "l"(g));
}
__device__ __forceinline__ void cp_commit() {
    asm volatile("cp.async.commit_group;\n" ::: "memory");
}
template <int N>
__device__ __forceinline__ void cp_wait() {
    asm volatile("cp.async.wait_group %0;\n" :: "n"(N) : "memory");
}

// ===========================================================================
// Kernel 1: fused projections  Y = x @ W^T + b  (times scale for K)
//   block tile 128x64, K-tile 32, 256 threads (8 warps, 4x2), tf32 MMA
//   grid.y: 0..7 -> Wk tiles, 8..15 -> Wq tiles, 16..31 -> Wv tiles
//   Output values are tf32-rounded so attention can cp.async them raw.
// ===========================================================================
#define PBM 128
#define PBN 64
#define PBK 32
#define PLDA 36
#define PNKT (DIN / PBK)   // 32

__global__ void __launch_bounds__(256) proj_kernel(
    const float* __restrict__ x,
    const float* __restrict__ Wk, const float* __restrict__ bk,
    const float* __restrict__ Wq, const float* __restrict__ bq,
    const float* __restrict__ Wv, const float* __restrict__ bv)
{
    __shared__ __align__(16) float As[PBM * PLDA];
    __shared__ __align__(16) float Bs[PBN * PLDA];

    int nt = blockIdx.y;
    const float* W;
    const float* bias;
    float* Y;
    int ncols;
    float scale;
    if (nt < 8)       { W = Wk; bias = bk; Y = g_K; ncols = DKQ; scale = 0.125f; }
    else if (nt < 16) { W = Wq; bias = bq; Y = g_Q; ncols = DKQ; scale = 1.0f; nt -= 8; }
    else              { W = Wv; bias = bv; Y = g_V; ncols = DVA; scale = 1.0f; nt -= 16; }
    const int n0 = nt * PBN;
    const int m0 = blockIdx.x * PBM;

    const int tid = threadIdx.x, lane = tid & 31, warp = tid >> 5;
    const int g = lane >> 2, t = lane & 3;
    const int wm = warp & 3, wn = warp >> 2;   // warp tile: rows wm*32, cols wn*32

    const int lr  = tid >> 3;   // loader row 0..31
    const int lc4 = tid & 7;    // loader float4 col 0..7

    const float* xp = x + (size_t)(m0 + lr) * DIN + lc4 * 4;
    const float* wp = W + (size_t)(n0 + lr) * DIN + lc4 * 4;

    float4 xa[4];
    float4 wa[2];
    float acc[2][4][4];
#pragma unroll
    for (int i = 0; i < 2; i++)
#pragma unroll
        for (int j = 0; j < 4; j++)
#pragma unroll
            for (int k = 0; k < 4; k++) acc[i][j][k] = 0.f;

    // prologue load + store
#pragma unroll
    for (int r = 0; r < 4; r++) xa[r] = *(const float4*)(xp + (size_t)r * 32 * DIN);
#pragma unroll
    for (int r = 0; r < 2; r++) wa[r] = *(const float4*)(wp + (size_t)r * 32 * DIN);
#pragma unroll
    for (int r = 0; r < 4; r++) {
        uint4 u4;
        u4.x = f2tf(xa[r].x); u4.y = f2tf(xa[r].y); u4.z = f2tf(xa[r].z); u4.w = f2tf(xa[r].w);
        *reinterpret_cast<uint4*>(&As[(lr + r * 32) * PLDA + lc4 * 4]) = u4;
    }
#pragma unroll
    for (int r = 0; r < 2; r++) {
        uint4 u4;
        u4.x = f2tf(wa[r].x); u4.y = f2tf(wa[r].y); u4.z = f2tf(wa[r].z); u4.w = f2tf(wa[r].w);
        *reinterpret_cast<uint4*>(&Bs[(lr + r * 32) * PLDA + lc4 * 4]) = u4;
    }
    __syncthreads();

    for (int kt = 0; kt < PNKT; kt++) {
        const int knext = (kt + 1) * PBK;
        if (kt + 1 < PNKT) {
#pragma unroll
            for (int r = 0; r < 4; r++) xa[r] = *(const float4*)(xp + (size_t)r * 32 * DIN + knext);
#pragma unroll
            for (int r = 0; r < 2; r++) wa[r] = *(const float4*)(wp + (size_t)r * 32 * DIN + knext);
        }
        // compute from smem
#pragma unroll
        for (int ks = 0; ks < 4; ks++) {
            const int k0 = ks * 8;
            uint32_t afr[2][4];
#pragma unroll
            for (int ms = 0; ms < 2; ms++) {
                const float* Ab = &As[(wm * 32 + ms * 16) * PLDA + k0];
                afr[ms][0] = fu(Ab[g * PLDA + t]);
                afr[ms][1] = fu(Ab[(g + 8) * PLDA + t]);
                afr[ms][2] = fu(Ab[g * PLDA + t + 4]);
                afr[ms][3] = fu(Ab[(g + 8) * PLDA + t + 4]);
            }
#pragma unroll
            for (int ns = 0; ns < 4; ns++) {
                const float* Bb = &Bs[(wn * 32 + ns * 8 + g) * PLDA + k0];
                uint32_t bfr[2];
                bfr[0] = fu(Bb[t]);
                bfr[1] = fu(Bb[t + 4]);
#pragma unroll
                for (int ms = 0; ms < 2; ms++) mma8(acc[ms][ns], afr[ms], bfr);
            }
        }
        __syncthreads();
        if (kt + 1 < PNKT) {
#pragma unroll
            for (int r = 0; r < 4; r++) {
                uint4 u4;
                u4.x = f2tf(xa[r].x); u4.y = f2tf(xa[r].y); u4.z = f2tf(xa[r].z); u4.w = f2tf(xa[r].w);
                *reinterpret_cast<uint4*>(&As[(lr + r * 32) * PLDA + lc4 * 4]) = u4;
            }
#pragma unroll
            for (int r = 0; r < 2; r++) {
                uint4 u4;
                u4.x = f2tf(wa[r].x); u4.y = f2tf(wa[r].y); u4.z = f2tf(wa[r].z); u4.w = f2tf(wa[r].w);
                *reinterpret_cast<uint4*>(&Bs[(lr + r * 32) * PLDA + lc4 * 4]) = u4;
            }
            __syncthreads();
        }
    }

    // epilogue: bias + scale, then tf32-round (so attention consumes raw bytes)
#pragma unroll
    for (int ms = 0; ms < 2; ms++) {
        const int row = m0 + wm * 32 + ms * 16;
#pragma unroll
        for (int ns = 0; ns < 4; ns++) {
            const int col = n0 + wn * 32 + ns * 8 + 2 * t;
            const float b0 = __ldg(&bias[col]);
            const float b1 = __ldg(&bias[col + 1]);
            float2 v0, v1;
            v0.x = __uint_as_float(f2tf((acc[ms][ns][0] + b0) * scale));
            v0.y = __uint_as_float(f2tf((acc[ms][ns][1] + b1) * scale));
            v1.x = __uint_as_float(f2tf((acc[ms][ns][2] + b0) * scale));
            v1.y = __uint_as_float(f2tf((acc[ms][ns][3] + b1) * scale));
            *reinterpret_cast<float2*>(&Y[(size_t)(row + g) * ncols + col]) = v0;
            *reinterpret_cast<float2*>(&Y[(size_t)(row + g + 8) * ncols + col]) = v1;
        }
    }
}

// ===========================================================================
// Kernel 2: flash attention v2
//   block = 128 i-rows x 1 head, 8 warps, warp tile 16 (i) x full 64 (j)
//   register-resident online softmax; cp.async double-buffered K/V tiles
// ===========================================================================
#define TI 128
#define TJ 64
#define KLD 68    // Ks row stride (floats): [j][64 hidden], 4g+t conflict-free
#define VLD 136   // Vs row stride (floats): [j][128 e], ≡8 mod 32 -> conflict-free
#define PLD 68    // per-warp P row stride

// smem: Ks 2*64*68 + Vs 2*64*136 + Ps 8*16*68 floats
static constexpr int ATTN_SMEM_FLOATS = 2 * TJ * KLD + 2 * TJ * VLD + 8 * 16 * PLD;
static constexpr int ATTN_SMEM_BYTES  = ATTN_SMEM_FLOATS * 4;   // 139264 B

__global__ void __launch_bounds__(256, 1) attn_kernel() {
    extern __shared__ __align__(16) float sm[];
    float* Ks = sm;                        // [2][TJ][KLD]
    float* Vs = Ks + 2 * TJ * KLD;         // [2][TJ][VLD]
    float* Ps = Vs + 2 * TJ * VLD;         // [8][16][PLD]

    const int h  = blockIdx.y;
    const int i0 = blockIdx.x * TI;
    const int tid = threadIdx.x, lane = tid & 31, warp = tid >> 5;
    const int g = lane >> 2, t = lane & 3;

    float* Pw = Ps + warp * 16 * PLD;
    const uint32_t s_ks = (uint32_t)__cvta_generic_to_shared(Ks);
    const uint32_t s_vs = (uint32_t)__cvta_generic_to_shared(Vs);

    // ---- Q fragments into registers (rows i0+warp*16 .. +15, head h) ----
    uint32_t qf[8][4];
    {
        const float* qb = g_K + (size_t)(i0 + warp * 16) * DKQ + h * DH;
#pragma unroll
        for (int ks = 0; ks < 8; ks++) {
            qf[ks][0] = fu(qb[(size_t)g * DKQ + ks * 8 + t]);
            qf[ks][1] = fu(qb[(size_t)(g + 8) * DKQ + ks * 8 + t]);
            qf[ks][2] = fu(qb[(size_t)g * DKQ + ks * 8 + t + 4]);
            qf[ks][3] = fu(qb[(size_t)(g + 8) * DKQ + ks * 8 + t + 4]);
        }
    }

    float m0 = -3.0e38f, m1 = -3.0e38f, l0 = 0.f, l1 = 0.f;
    float Oacc[16][4];
#pragma unroll
    for (int i = 0; i < 16; i++)
#pragma unroll
        for (int j = 0; j < 4; j++) Oacc[i][j] = 0.f;

    // ---- tile loader: K tile 64x64, V tile 64x128, via cp.async 16B ----
    auto load_tile = [&](int jt, int buf) {
        const float* ksrc = g_Q + (size_t)(jt * TJ) * DKQ + h * DH;
        const uint32_t kdst = s_ks + (uint32_t)(buf * TJ * KLD) * 4;
#pragma unroll
        for (int i = 0; i < 4; i++) {
            const int c = i * 256 + tid;            // 0..1023
            const int r = c >> 4, c4 = c & 15;
            cp16(kdst + (uint32_t)(r * KLD + c4 * 4) * 4,
                 ksrc + (size_t)r * DKQ + c4 * 4);
        }
        const float* vsrc = g_V + (size_t)(jt * TJ) * DVA + h * DV;
        const uint32_t vdst = s_vs + (uint32_t)(buf * TJ * VLD) * 4;
#pragma unroll
        for (int i = 0; i < 8; i++) {
            const int c = i * 256 + tid;            // 0..2047
            const int r = c >> 5, c4 = c & 31;
            cp16(vdst + (uint32_t)(r * VLD + c4 * 4) * 4,
                 vsrc + (size_t)r * DVA + c4 * 4);
        }
    };

    load_tile(0, 0);
    cp_commit();

    for (int jt = 0; jt < SEQ / TJ; ++jt) {
        const int cur = jt & 1;
        if (jt + 1 < SEQ / TJ) load_tile(jt + 1, cur ^ 1);
        cp_commit();
        cp_wait<1>();
        __syncthreads();                 // tile jt visible to all warps

        const float* Kb = Ks + cur * TJ * KLD;
        const float* Vb = Vs + cur * TJ * VLD;

        // --- S = Q' K'^T (16 x 64 per warp) ---
        float Sacc[8][4];
#pragma unroll
        for (int i = 0; i < 8; i++)
#pragma unroll
            for (int j = 0; j < 4; j++) Sacc[i][j] = 0.f;
#pragma unroll
        for (int ks = 0; ks < 8; ks++) {
            const int k0 = ks * 8;
#pragma unroll
            for (int ns = 0; ns < 8; ns++) {
                const float* Bb = Kb + (ns * 8 + g) * KLD + k0;
                uint32_t b[2] = { fu(Bb[t]), fu(Bb[t + 4]) };
                mma8(Sacc[ns], qf[ks], b);
            }
        }

        // --- register-resident online softmax (rows g and g+8) ---
        float t0 = -3.0e38f, t1 = -3.0e38f;
#pragma unroll
        for (int ns = 0; ns < 8; ns++) {
            t0 = fmaxf(t0, fmaxf(Sacc[ns][0], Sacc[ns][1]));
            t1 = fmaxf(t1, fmaxf(Sacc[ns][2], Sacc[ns][3]));
        }
        t0 = fmaxf(t0, __shfl_xor_sync(0xffffffffu, t0, 1));
        t0 = fmaxf(t0, __shfl_xor_sync(0xffffffffu, t0, 2));
        t1 = fmaxf(t1, __shfl_xor_sync(0xffffffffu, t1, 1));
        t1 = fmaxf(t1, __shfl_xor_sync(0xffffffffu, t1, 2));
        const float nm0 = fmaxf(m0, t0), nm1 = fmaxf(m1, t1);
        const float a0 = __expf(m0 - nm0), a1 = __expf(m1 - nm1);
        float s0 = 0.f, s1 = 0.f;
#pragma unroll
        for (int ns = 0; ns < 8; ns++) {
            float p0 = __expf(Sacc[ns][0] - nm0);
            float p1 = __expf(Sacc[ns][1] - nm0);
            float p2 = __expf(Sacc[ns][2] - nm1);
            float p3 = __expf(Sacc[ns][3] - nm1);
            s0 += p0 + p1; s1 += p2 + p3;
            Sacc[ns][0] = __uint_as_float(f2tf(p0));
            Sacc[ns][1] = __uint_as_float(f2tf(p1));
            Sacc[ns][2] = __uint_as_float(f2tf(p2));
            Sacc[ns][3] = __uint_as_float(f2tf(p3));
        }
        s0 += __shfl_xor_sync(0xffffffffu, s0, 1);
        s0 += __shfl_xor_sync(0xffffffffu, s0, 2);
        s1 += __shfl_xor_sync(0xffffffffu, s1, 1);
        s1 += __shfl_xor_sync(0xffffffffu, s1, 2);
        m0 = nm0; m1 = nm1;
        l0 = l0 * a0 + s0;
        l1 = l1 * a1 + s1;

        // --- P -> warp-private smem for A-fragment reload (no block barrier) ---
#pragma unroll
        for (int ns = 0; ns < 8; ns++) {
            *reinterpret_cast<float2*>(&Pw[g * PLD + ns * 8 + 2 * t]) =
                make_float2(Sacc[ns][0], Sacc[ns][1]);
            *reinterpret_cast<float2*>(&Pw[(g + 8) * PLD + ns * 8 + 2 * t]) =
                make_float2(Sacc[ns][2], Sacc[ns][3]);
        }
        __syncwarp();

        // --- rescale O ---
#pragma unroll
        for (int ns = 0; ns < 16; ns++) {
            Oacc[ns][0] *= a0; Oacc[ns][1] *= a0;
            Oacc[ns][2] *= a1; Oacc[ns][3] *= a1;
        }

        // --- O += P @ V (16 x 128 per warp) ---
#pragma unroll
        for (int ks = 0; ks < 8; ks++) {
            const int k0 = ks * 8;
            uint32_t a[4];
            a[0] = fu(Pw[g * PLD + k0 + t]);
            a[1] = fu(Pw[(g + 8) * PLD + k0 + t]);
            a[2] = fu(Pw[g * PLD + k0 + t + 4]);
            a[3] = fu(Pw[(g + 8) * PLD + k0 + t + 4]);
            const float* Vr0 = Vb + (k0 + t) * VLD + g;
            const float* Vr1 = Vb + (k0 + t + 4) * VLD + g;
#pragma unroll
            for (int ns = 0; ns < 16; ns++) {
                uint32_t b[2] = { fu(Vr0[ns * 8]), fu(Vr1[ns * 8]) };
                mma8(Oacc[ns], a, b);
            }
        }
        __syncthreads();                 // all warps done reading this buffer
    }

    // ---- epilogue: divide by denominator, store per-head output ----
    {
        const float r0 = 1.f / l0;
        const float r1 = 1.f / l1;
        float* dst = g_Oh[h] + (size_t)(i0 + warp * 16) * DV;
#pragma unroll
        for (int ns = 0; ns < 16; ns++) {
            const int col = ns * 8 + 2 * t;
            *reinterpret_cast<float2*>(&dst[(size_t)g * DV + col]) =
                make_float2(Oacc[ns][0] * r0, Oacc[ns][1] * r0);
            *reinterpret_cast<float2*>(&dst[(size_t)(g + 8) * DV + col]) =
                make_float2(Oacc[ns][2] * r1, Oacc[ns][3] * r1);
        }
    }
}

// ===========================================================================
// Kernel 3: sum heads + LayerNorm over last dim (128)
// ===========================================================================
__global__ void __launch_bounds__(128) ln_kernel(
    const float* __restrict__ ln_w, const float* __restrict__ ln_b,
    float* __restrict__ out)
{
    const int i = blockIdx.x;
    const int e = threadIdx.x;     // 0..127
    const int lane = e & 31, w = e >> 5;

    float s = 0.f;
#pragma unroll
    for (int h = 0; h < NH; h++) s += g_Oh[h][(size_t)i * DV + e];

    __shared__ float red[4];
    float v = s;
#pragma unroll
    for (int o = 16; o > 0; o >>= 1) v += __shfl_xor_sync(0xffffffffu, v, o);
    if (lane == 0) red[w] = v;
    __syncthreads();
    const float mean = (red[0] + red[1] + red[2] + red[3]) * (1.f / 128.f);
    const float d = s - mean;

    float vv = d * d;
#pragma unroll
    for (int o = 16; o > 0; o >>= 1) vv += __shfl_xor_sync(0xffffffffu, vv, o);
    __syncthreads();
    if (lane == 0) red[w] = vv;
    __syncthreads();
    const float var = (red[0] + red[1] + red[2] + red[3]) * (1.f / 128.f);

    out[(size_t)i * DV + e] = d * rsqrtf(var + 1e-5f) * __ldg(&ln_w[e]) + __ldg(&ln_b[e]);
}

// ===========================================================================
extern "C" void kernel_launch(void* const* d_in, const int* in_sizes, int n_in,
                              void* d_out, int out_size) {
    (void)in_sizes; (void)n_in; (void)out_size;
    const float* x  = (const float*)d_in[0];
    const float* Wk = (const float*)d_in[1];
    const float* bk = (const float*)d_in[2];
    const float* Wq = (const float*)d_in[3];
    const float* bq = (const float*)d_in[4];
    const float* Wv = (const float*)d_in[5];
    const float* bv = (const float*)d_in[6];
    const float* lw = (const float*)d_in[7];
    const float* lb = (const float*)d_in[8];
    float* out = (float*)d_out;

    // projections: grid.y = 8 (Wk) + 8 (Wq) + 16 (Wv) tiles of 64 cols
    proj_kernel<<<dim3(SEQ / PBM, 32), 256>>>(x, Wk, bk, Wq, bq, Wv, bv);

    cudaFuncSetAttribute(attn_kernel, cudaFuncAttributeMaxDynamicSharedMemorySize,
                         ATTN_SMEM_BYTES);
    attn_kernel<<<dim3(SEQ / TI, NH), 256, ATTN_SMEM_BYTES>>>();

    ln_kernel<<<SEQ, 128>>>(lw, lb, out);
}